// round 1
// baseline (speedup 1.0000x reference)
#include <cuda_runtime.h>
#include <math.h>

// Fixed problem shapes (B=256, R=512, D=64, N=100000, E=3.2M)
#define RR   512
#define DD   64
#define BB   256
#define DIN  132          // 2*DD + 4
#define TBL  1024         // hash table slots (load factor <= 0.25)
#define TBLM (TBL - 1)
#define EMPTY_KEY (-1)

// Scratch (device globals: no allocation allowed in kernel_launch)
__device__ int g_Mq[BB * RR];     // per-representative-b relation counts
__device__ int g_relc[RR];        // global relation histogram
__device__ int g_keys[TBL];       // hash: entity id  (or EMPTY_KEY)
__device__ int g_vals[TBL];       // hash: representative b (min b with that entity)

__device__ __forceinline__ unsigned hash_ent(int x) {
    return ((unsigned)x * 2654435761u) >> 16;
}

// ---------------------------------------------------------------- clear
__global__ void k_clear() {
    int i = blockIdx.x * blockDim.x + threadIdx.x;
    int stride = gridDim.x * blockDim.x;
    for (int j = i; j < BB * RR; j += stride) g_Mq[j] = 0;
    if (i < RR)  g_relc[i] = 0;
    if (i < TBL) { g_keys[i] = EMPTY_KEY; g_vals[i] = 0x7FFFFFFF; }
}

// ---------------------------------------------------------------- build hash
__global__ void k_build(const int* __restrict__ qent, int B) {
    int b = blockIdx.x * blockDim.x + threadIdx.x;
    if (b >= B) return;
    int ent = qent[b];
    unsigned s = hash_ent(ent) & TBLM;
    while (true) {
        int prev = atomicCAS(&g_keys[s], EMPTY_KEY, ent);
        if (prev == EMPTY_KEY || prev == ent) {
            atomicMin(&g_vals[s], b);   // representative = min b (deterministic)
            break;
        }
        s = (s + 1) & TBLM;
    }
}

// ---------------------------------------------------------------- edge scan
__device__ __forceinline__ void process_edge(int h, int t, int y,
                                             const int* __restrict__ skeys,
                                             const int* __restrict__ svals,
                                             int* __restrict__ shist) {
    atomicAdd(&shist[y], 1);
    // head lookup
    unsigned s = hash_ent(h) & TBLM;
    while (true) {
        int k = skeys[s];
        if (k == h) { atomicAdd(&g_Mq[svals[s] * RR + y], 1); break; }
        if (k == EMPTY_KEY) break;
        s = (s + 1) & TBLM;
    }
    if (t != h) {   // self-loop counted once
        s = hash_ent(t) & TBLM;
        while (true) {
            int k = skeys[s];
            if (k == t) { atomicAdd(&g_Mq[svals[s] * RR + y], 1); break; }
            if (k == EMPTY_KEY) break;
            s = (s + 1) & TBLM;
        }
    }
}

__global__ __launch_bounds__(256) void k_edges(const int* __restrict__ heads,
                                               const int* __restrict__ tails,
                                               const int* __restrict__ types,
                                               int E) {
    __shared__ int skeys[TBL];
    __shared__ int svals[TBL];
    __shared__ int shist[RR];
    int tid = threadIdx.x;
    for (int j = tid; j < TBL; j += 256) { skeys[j] = g_keys[j]; svals[j] = g_vals[j]; }
    for (int j = tid; j < RR; j += 256) shist[j] = 0;
    __syncthreads();

    const int4* h4 = (const int4*)heads;
    const int4* t4 = (const int4*)tails;
    const int4* y4 = (const int4*)types;
    int E4 = E >> 2;
    int gid = blockIdx.x * blockDim.x + tid;
    int stride = gridDim.x * blockDim.x;
    for (int i = gid; i < E4; i += stride) {
        int4 h = h4[i];
        int4 t = t4[i];
        int4 y = y4[i];
        process_edge(h.x, t.x, y.x, skeys, svals, shist);
        process_edge(h.y, t.y, y.y, skeys, svals, shist);
        process_edge(h.z, t.z, y.z, skeys, svals, shist);
        process_edge(h.w, t.w, y.w, skeys, svals, shist);
    }
    // remainder (E % 4) — handled by first few threads of block 0
    if (blockIdx.x == 0 && tid < (E & 3)) {
        int e = (E4 << 2) + tid;
        process_edge(heads[e], tails[e], types[e], skeys, svals, shist);
    }
    __syncthreads();
    for (int j = tid; j < RR; j += 256) {
        int v = shist[j];
        if (v) atomicAdd(&g_relc[j], v);
    }
}

// ---------------------------------------------------------------- epilogue
__global__ __launch_bounds__(128) void k_final(
    const float* __restrict__ rel_emb,   // [B, R, D]
    const int* __restrict__ qrels,
    const int* __restrict__ qent,
    const float* __restrict__ W1, const float* __restrict__ b1,
    const float* __restrict__ W2, const float* __restrict__ b2,
    const float* __restrict__ W3, const float* __restrict__ b3,
    const float* __restrict__ W4, const float* __restrict__ b4,
    float* __restrict__ out, int E, float density) {
    int b = blockIdx.x;
    int tid = threadIdx.x;
    __shared__ float scnt[RR];
    __shared__ float sx[DIN];
    __shared__ float sh1[DD];
    __shared__ float sh2[32];
    __shared__ float sg[16];
    __shared__ int sdeg;
    __shared__ int srep;

    if (tid == 0) {
        int ent = qent[b];
        unsigned s = hash_ent(ent) & TBLM;
        int rep = 0;
        while (true) {
            int k = g_keys[s];
            if (k == ent) { rep = g_vals[s]; break; }
            if (k == EMPTY_KEY) break;   // cannot happen: all query entities inserted
            s = (s + 1) & TBLM;
        }
        srep = rep;
        sdeg = 0;
    }
    __syncthreads();
    int rep = srep;
    int degloc = 0;
    for (int r = tid; r < RR; r += 128) {
        int c = g_Mq[rep * RR + r];
        scnt[r] = (float)c;
        degloc += c;
    }
    #pragma unroll
    for (int o = 16; o; o >>= 1) degloc += __shfl_down_sync(0xffffffffu, degloc, o);
    if ((tid & 31) == 0) atomicAdd(&sdeg, degloc);   // integer sum: deterministic
    __syncthreads();
    float deg = (float)sdeg;
    float inv = 1.0f / fmaxf(deg, 1.0f);

    int qr = qrels[b];
    if (tid < DD) {
        // query relation embedding
        sx[tid] = rel_emb[((size_t)b * RR + qr) * DD + tid];
        // masked mean over incident relations (skip zero-count rows: ~60 of 512)
        float acc = 0.0f;
        const float* base = rel_emb + (size_t)b * RR * DD + tid;
        for (int r = 0; r < RR; r++) {
            float c = scnt[r];                 // uniform across warp (smem broadcast)
            if (c != 0.0f) acc = fmaf(c, base[(size_t)r * DD], acc);
        }
        sx[DD + tid] = acc * inv;
    }
    if (tid == 0) {
        float freq = fminf((float)g_relc[qr] / (float)E, 1.0f);
        float degn = fminf(deg / (float)E, 1.0f);
        sx[128] = freq;
        sx[129] = degn;
        sx[130] = freq;
        sx[131] = density;
    }
    __syncthreads();

    // 132 -> 64 -> 32 -> 16 -> 1 MLP (weights L2-hot across the 256 blocks)
    if (tid < 64) {
        float acc = b1[tid];
        #pragma unroll 4
        for (int i = 0; i < DIN; i++) acc = fmaf(sx[i], W1[i * 64 + tid], acc);
        sh1[tid] = fmaxf(acc, 0.0f);
    }
    __syncthreads();
    if (tid < 32) {
        float acc = b2[tid];
        #pragma unroll 4
        for (int i = 0; i < 64; i++) acc = fmaf(sh1[i], W2[i * 32 + tid], acc);
        sh2[tid] = fmaxf(acc, 0.0f);
    }
    __syncthreads();
    if (tid < 16) {
        float acc = b3[tid];
        #pragma unroll
        for (int i = 0; i < 32; i++) acc = fmaf(sh2[i], W3[i * 16 + tid], acc);
        sg[tid] = fmaxf(acc, 0.0f);
    }
    __syncthreads();
    if (tid == 0) {
        float acc = b4[0];
        #pragma unroll
        for (int i = 0; i < 16; i++) acc = fmaf(sg[i], W4[i], acc);
        out[b] = 1.0f / (1.0f + expf(-acc));
    }
}

// ---------------------------------------------------------------- launch
extern "C" void kernel_launch(void* const* d_in, const int* in_sizes, int n_in,
                              void* d_out, int out_size) {
    const float* rel_emb = (const float*)d_in[0];
    const int*   qrels   = (const int*)d_in[1];
    const int*   qent    = (const int*)d_in[2];
    const int*   eidx    = (const int*)d_in[3];
    const int*   etype   = (const int*)d_in[4];
    // Weights indexed from the end (robust to scalar inputs being present or not)
    const float* W1 = (const float*)d_in[n_in - 8];
    const float* b1 = (const float*)d_in[n_in - 7];
    const float* W2 = (const float*)d_in[n_in - 6];
    const float* b2 = (const float*)d_in[n_in - 5];
    const float* W3 = (const float*)d_in[n_in - 4];
    const float* b3 = (const float*)d_in[n_in - 3];
    const float* W4 = (const float*)d_in[n_in - 2];
    const float* b4 = (const float*)d_in[n_in - 1];

    int B = in_sizes[1];          // 256
    int E = in_sizes[4];          // 3,200,000
    const int* heads = eidx;
    const int* tails = eidx + E;

    double Nd = 100000.0;         // fixed problem
    float density = (float)fmin((double)E / (Nd * Nd), 1.0);

    k_clear<<<(BB * RR + 255) / 256, 256>>>();
    k_build<<<(B + 255) / 256, 256>>>(qent, B);
    k_edges<<<592, 256>>>(heads, tails, etype, E);
    k_final<<<B, 128>>>(rel_emb, qrels, qent,
                        W1, b1, W2, b2, W3, b3, W4, b4,
                        (float*)d_out, E, density);
}

// round 2
// speedup vs baseline: 1.2379x; 1.2379x over previous
#include <cuda_runtime.h>
#include <math.h>

// Fixed problem shapes (B=256, R=512, D=64, N=100000, E=3.2M)
#define RR   512
#define DD   64
#define BB   256
#define DIN  132          // 2*DD + 4
#define TBL  1024         // hash table slots (load factor <= 0.25)
#define TBLM (TBL - 1)
#define EMPTY_KEY (-1)

// Scratch (device globals: no allocation allowed in kernel_launch)
__device__ int g_Mq[BB * RR];     // per-representative-b relation counts
__device__ int g_relc[RR];        // global relation histogram
__device__ int g_keys[TBL];       // hash: entity id  (or EMPTY_KEY)
__device__ int g_vals[TBL];       // hash: representative b (min b with that entity)

__device__ __forceinline__ unsigned hash_ent(int x) {
    return ((unsigned)x * 2654435761u) >> 16;
}

// ---------------------------------------------------------------- clear
__global__ void k_clear() {
    int i = blockIdx.x * blockDim.x + threadIdx.x;
    int stride = gridDim.x * blockDim.x;
    for (int j = i; j < BB * RR; j += stride) g_Mq[j] = 0;
    if (i < RR)  g_relc[i] = 0;
    if (i < TBL) { g_keys[i] = EMPTY_KEY; g_vals[i] = 0x7FFFFFFF; }
}

// ---------------------------------------------------------------- build hash
__global__ void k_build(const int* __restrict__ qent, int B) {
    int b = blockIdx.x * blockDim.x + threadIdx.x;
    if (b >= B) return;
    int ent = qent[b];
    unsigned s = hash_ent(ent) & TBLM;
    while (true) {
        int prev = atomicCAS(&g_keys[s], EMPTY_KEY, ent);
        if (prev == EMPTY_KEY || prev == ent) {
            atomicMin(&g_vals[s], b);   // representative = min b (deterministic)
            break;
        }
        s = (s + 1) & TBLM;
    }
}

// ---------------------------------------------------------------- edge scan
__device__ __forceinline__ void process_edge(int h, int t, int y,
                                             const int* __restrict__ skeys,
                                             const int* __restrict__ svals,
                                             int* __restrict__ shist) {
    atomicAdd(&shist[y], 1);
    // head lookup
    unsigned s = hash_ent(h) & TBLM;
    while (true) {
        int k = skeys[s];
        if (k == h) { atomicAdd(&g_Mq[svals[s] * RR + y], 1); break; }
        if (k == EMPTY_KEY) break;
        s = (s + 1) & TBLM;
    }
    if (t != h) {   // self-loop counted once
        s = hash_ent(t) & TBLM;
        while (true) {
            int k = skeys[s];
            if (k == t) { atomicAdd(&g_Mq[svals[s] * RR + y], 1); break; }
            if (k == EMPTY_KEY) break;
            s = (s + 1) & TBLM;
        }
    }
}

__global__ __launch_bounds__(256) void k_edges(const int* __restrict__ heads,
                                               const int* __restrict__ tails,
                                               const int* __restrict__ types,
                                               int E) {
    __shared__ int skeys[TBL];
    __shared__ int svals[TBL];
    __shared__ int shist[RR];
    int tid = threadIdx.x;
    for (int j = tid; j < TBL; j += 256) { skeys[j] = g_keys[j]; svals[j] = g_vals[j]; }
    for (int j = tid; j < RR; j += 256) shist[j] = 0;
    __syncthreads();

    const int4* h4 = (const int4*)heads;
    const int4* t4 = (const int4*)tails;
    const int4* y4 = (const int4*)types;
    int E4 = E >> 2;
    int gid = blockIdx.x * blockDim.x + tid;
    int stride = gridDim.x * blockDim.x;
    for (int i = gid; i < E4; i += stride) {
        int4 h = h4[i];
        int4 t = t4[i];
        int4 y = y4[i];
        process_edge(h.x, t.x, y.x, skeys, svals, shist);
        process_edge(h.y, t.y, y.y, skeys, svals, shist);
        process_edge(h.z, t.z, y.z, skeys, svals, shist);
        process_edge(h.w, t.w, y.w, skeys, svals, shist);
    }
    // remainder (E % 4) — handled by first few threads of block 0
    if (blockIdx.x == 0 && tid < (E & 3)) {
        int e = (E4 << 2) + tid;
        process_edge(heads[e], tails[e], types[e], skeys, svals, shist);
    }
    __syncthreads();
    for (int j = tid; j < RR; j += 256) {
        int v = shist[j];
        if (v) atomicAdd(&g_relc[j], v);
    }
}

// ---------------------------------------------------------------- epilogue
// 256 threads. Ballot-compact nonzero (r, cnt) pairs, then branch-free dense
// accumulation with a 64(d) x 4(chunk) layout.
__global__ __launch_bounds__(256) void k_final(
    const float* __restrict__ rel_emb,   // [B, R, D]
    const int* __restrict__ qrels,
    const int* __restrict__ qent,
    const float* __restrict__ W1, const float* __restrict__ b1,
    const float* __restrict__ W2, const float* __restrict__ b2,
    const float* __restrict__ W3, const float* __restrict__ b3,
    const float* __restrict__ W4, const float* __restrict__ b4,
    float* __restrict__ out, int E, float density) {
    int b = blockIdx.x;
    int tid = threadIdx.x;
    int lane = tid & 31;
    int w = tid >> 5;

    __shared__ float scnt[RR];     // compacted counts (only first nnz valid)
    __shared__ int   sridx[RR];    // compacted relation indices
    __shared__ int   scount[16];   // per-segment nonzero counts
    __shared__ int   soff[16];     // per-segment offsets
    __shared__ float spart[256];   // partial accumulators
    __shared__ float sx[DIN];
    __shared__ float sh1[DD];
    __shared__ float sh2[32];
    __shared__ float sg[16];
    __shared__ int sdeg;
    __shared__ int srep;
    __shared__ int snnz;

    if (tid == 0) {
        int ent = qent[b];
        unsigned s = hash_ent(ent) & TBLM;
        int rep = 0;
        while (true) {
            int k = g_keys[s];
            if (k == ent) { rep = g_vals[s]; break; }
            if (k == EMPTY_KEY) break;
            s = (s + 1) & TBLM;
        }
        srep = rep;
        sdeg = 0;
    }
    __syncthreads();
    int rep = srep;

    // Load Mq row (2 entries per thread), degree + ballot compaction
    int c0 = g_Mq[rep * RR + tid];
    int c1 = g_Mq[rep * RR + 256 + tid];
    int dsum = c0 + c1;
    #pragma unroll
    for (int o = 16; o; o >>= 1) dsum += __shfl_down_sync(0xffffffffu, dsum, o);
    if (lane == 0) atomicAdd(&sdeg, dsum);   // integer: deterministic

    unsigned bal0 = __ballot_sync(0xffffffffu, c0 != 0);
    unsigned bal1 = __ballot_sync(0xffffffffu, c1 != 0);
    if (lane == 0) { scount[w] = __popc(bal0); scount[8 + w] = __popc(bal1); }
    __syncthreads();
    if (tid == 0) {
        int acc = 0;
        #pragma unroll
        for (int s = 0; s < 16; s++) { soff[s] = acc; acc += scount[s]; }
        snnz = acc;
    }
    __syncthreads();
    unsigned ltmask = (1u << lane) - 1u;
    if (c0) {
        int p = soff[w] + __popc(bal0 & ltmask);
        sridx[p] = tid;        scnt[p] = (float)c0;
    }
    if (c1) {
        int p = soff[8 + w] + __popc(bal1 & ltmask);
        sridx[p] = 256 + tid;  scnt[p] = (float)c1;
    }
    __syncthreads();

    int nnz = snnz;
    float deg = (float)sdeg;
    float inv = 1.0f / fmaxf(deg, 1.0f);

    // Dense accumulation over compacted entries: thread = (d, j)
    {
        int d = tid & 63;
        int j = tid >> 6;
        const float* base = rel_emb + (size_t)b * RR * DD + d;
        float acc = 0.0f;
        #pragma unroll 2
        for (int i = j; i < nnz; i += 4)
            acc = fmaf(scnt[i], base[(size_t)sridx[i] * DD], acc);
        spart[tid] = acc;
    }

    int qr = qrels[b];
    if (tid < DD)
        sx[tid] = rel_emb[((size_t)b * RR + qr) * DD + tid];
    __syncthreads();
    if (tid < DD) {
        float s = ((spart[tid] + spart[64 + tid]) +
                   (spart[128 + tid] + spart[192 + tid]));  // fixed order
        sx[DD + tid] = s * inv;
    }
    if (tid == 0) {
        float freq = fminf((float)g_relc[qr] / (float)E, 1.0f);
        float degn = fminf(deg / (float)E, 1.0f);
        sx[128] = freq;
        sx[129] = degn;
        sx[130] = freq;
        sx[131] = density;
    }
    __syncthreads();

    // 132 -> 64 -> 32 -> 16 -> 1 MLP (weights L2-hot across the 256 blocks)
    if (tid < 64) {
        float acc = b1[tid];
        #pragma unroll 4
        for (int i = 0; i < DIN; i++) acc = fmaf(sx[i], W1[i * 64 + tid], acc);
        sh1[tid] = fmaxf(acc, 0.0f);
    }
    __syncthreads();
    if (tid < 32) {
        float acc = b2[tid];
        #pragma unroll 4
        for (int i = 0; i < 64; i++) acc = fmaf(sh1[i], W2[i * 32 + tid], acc);
        sh2[tid] = fmaxf(acc, 0.0f);
    }
    __syncthreads();
    if (tid < 16) {
        float acc = b3[tid];
        #pragma unroll
        for (int i = 0; i < 32; i++) acc = fmaf(sh2[i], W3[i * 16 + tid], acc);
        sg[tid] = fmaxf(acc, 0.0f);
    }
    __syncthreads();
    if (tid == 0) {
        float acc = b4[0];
        #pragma unroll
        for (int i = 0; i < 16; i++) acc = fmaf(sg[i], W4[i], acc);
        out[b] = 1.0f / (1.0f + expf(-acc));
    }
}

// ---------------------------------------------------------------- launch
extern "C" void kernel_launch(void* const* d_in, const int* in_sizes, int n_in,
                              void* d_out, int out_size) {
    const float* rel_emb = (const float*)d_in[0];
    const int*   qrels   = (const int*)d_in[1];
    const int*   qent    = (const int*)d_in[2];
    const int*   eidx    = (const int*)d_in[3];
    const int*   etype   = (const int*)d_in[4];
    // Weights indexed from the end (robust to scalar inputs being present or not)
    const float* W1 = (const float*)d_in[n_in - 8];
    const float* b1 = (const float*)d_in[n_in - 7];
    const float* W2 = (const float*)d_in[n_in - 6];
    const float* b2 = (const float*)d_in[n_in - 5];
    const float* W3 = (const float*)d_in[n_in - 4];
    const float* b3 = (const float*)d_in[n_in - 3];
    const float* W4 = (const float*)d_in[n_in - 2];
    const float* b4 = (const float*)d_in[n_in - 1];

    int B = in_sizes[1];          // 256
    int E = in_sizes[4];          // 3,200,000
    const int* heads = eidx;
    const int* tails = eidx + E;

    double Nd = 100000.0;         // fixed problem
    float density = (float)fmin((double)E / (Nd * Nd), 1.0);

    k_clear<<<(BB * RR + 255) / 256, 256>>>();
    k_build<<<(B + 255) / 256, 256>>>(qent, B);
    k_edges<<<592, 256>>>(heads, tails, etype, E);
    k_final<<<B, 256>>>(rel_emb, qrels, qent,
                        W1, b1, W2, b2, W3, b3, W4, b4,
                        (float*)d_out, E, density);
}

// round 3
// speedup vs baseline: 1.2998x; 1.0500x over previous
#include <cuda_runtime.h>
#include <math.h>

// Fixed problem shapes (B=256, R=512, D=64, N=100000, E=3.2M)
#define RR   512
#define DD   64
#define BB   256
#define DIN  132          // 2*DD + 4
#define TBL  1024         // hash table slots (load factor <= 0.25)
#define TBLM (TBL - 1)
#define EMPTY_KEY (-1)
#define NCHUNK 16         // gather chunks per b

// Scratch (device globals: no allocation allowed in kernel_launch)
__device__ int   g_Mq[BB * RR];       // per-representative-b relation counts
__device__ int   g_relc[RR];          // global relation histogram
__device__ int   g_keys[TBL];         // hash: entity id (or EMPTY_KEY)
__device__ int   g_vals[TBL];         // hash: representative b (min b)
__device__ int   g_cidx[BB * RR];     // compacted relation indices per b
__device__ float g_ccnt[BB * RR];     // compacted counts per b
__device__ int   g_nnz[BB];
__device__ int   g_deg[BB];
__device__ float g_part[BB * NCHUNK * DD];   // gather partial sums

__device__ __forceinline__ unsigned hash_ent(int x) {
    return ((unsigned)x * 2654435761u) >> 16;
}

// ---------------------------------------------------------------- clear
__global__ void k_clear() {
    int i = blockIdx.x * blockDim.x + threadIdx.x;
    int stride = gridDim.x * blockDim.x;
    for (int j = i; j < BB * RR; j += stride) g_Mq[j] = 0;
    if (i < RR)  g_relc[i] = 0;
    if (i < TBL) { g_keys[i] = EMPTY_KEY; g_vals[i] = 0x7FFFFFFF; }
}

// ---------------------------------------------------------------- build hash
__global__ void k_build(const int* __restrict__ qent, int B) {
    int b = blockIdx.x * blockDim.x + threadIdx.x;
    if (b >= B) return;
    int ent = qent[b];
    unsigned s = hash_ent(ent) & TBLM;
    while (true) {
        int prev = atomicCAS(&g_keys[s], EMPTY_KEY, ent);
        if (prev == EMPTY_KEY || prev == ent) {
            atomicMin(&g_vals[s], b);   // representative = min b (deterministic)
            break;
        }
        s = (s + 1) & TBLM;
    }
}

// ---------------------------------------------------------------- edge scan
__device__ __forceinline__ void process_edge(int h, int t, int y,
                                             const int* __restrict__ skeys,
                                             const int* __restrict__ svals,
                                             int* __restrict__ shist) {
    atomicAdd(&shist[y], 1);
    unsigned s = hash_ent(h) & TBLM;
    while (true) {
        int k = skeys[s];
        if (k == h) { atomicAdd(&g_Mq[svals[s] * RR + y], 1); break; }
        if (k == EMPTY_KEY) break;
        s = (s + 1) & TBLM;
    }
    if (t != h) {   // self-loop counted once
        s = hash_ent(t) & TBLM;
        while (true) {
            int k = skeys[s];
            if (k == t) { atomicAdd(&g_Mq[svals[s] * RR + y], 1); break; }
            if (k == EMPTY_KEY) break;
            s = (s + 1) & TBLM;
        }
    }
}

__global__ __launch_bounds__(256) void k_edges(const int* __restrict__ heads,
                                               const int* __restrict__ tails,
                                               const int* __restrict__ types,
                                               int E) {
    __shared__ int skeys[TBL];
    __shared__ int svals[TBL];
    __shared__ int shist[RR];
    int tid = threadIdx.x;
    for (int j = tid; j < TBL; j += 256) { skeys[j] = g_keys[j]; svals[j] = g_vals[j]; }
    for (int j = tid; j < RR; j += 256) shist[j] = 0;
    __syncthreads();

    const int4* h4 = (const int4*)heads;
    const int4* t4 = (const int4*)tails;
    const int4* y4 = (const int4*)types;
    int E4 = E >> 2;
    int gid = blockIdx.x * blockDim.x + tid;
    int stride = gridDim.x * blockDim.x;
    for (int i = gid; i < E4; i += stride) {
        int4 h = h4[i];
        int4 t = t4[i];
        int4 y = y4[i];
        process_edge(h.x, t.x, y.x, skeys, svals, shist);
        process_edge(h.y, t.y, y.y, skeys, svals, shist);
        process_edge(h.z, t.z, y.z, skeys, svals, shist);
        process_edge(h.w, t.w, y.w, skeys, svals, shist);
    }
    if (blockIdx.x == 0 && tid < (E & 3)) {
        int e = (E4 << 2) + tid;
        process_edge(heads[e], tails[e], types[e], skeys, svals, shist);
    }
    __syncthreads();
    for (int j = tid; j < RR; j += 256) {
        int v = shist[j];
        if (v) atomicAdd(&g_relc[j], v);
    }
}

// ---------------------------------------------------------------- compact
// One block per b: load Mq row, deg, ballot-compact nonzeros to global.
__global__ __launch_bounds__(256) void k_compact(const int* __restrict__ qent) {
    int b = blockIdx.x;
    int tid = threadIdx.x;
    int lane = tid & 31;
    int w = tid >> 5;
    __shared__ int scount[16];
    __shared__ int soff[16];
    __shared__ int sdeg;
    __shared__ int srep;

    if (tid == 0) {
        int ent = qent[b];
        unsigned s = hash_ent(ent) & TBLM;
        int rep = 0;
        while (true) {
            int k = g_keys[s];
            if (k == ent) { rep = g_vals[s]; break; }
            if (k == EMPTY_KEY) break;
            s = (s + 1) & TBLM;
        }
        srep = rep;
        sdeg = 0;
    }
    __syncthreads();
    int rep = srep;

    int c0 = g_Mq[rep * RR + tid];
    int c1 = g_Mq[rep * RR + 256 + tid];
    int dsum = c0 + c1;
    #pragma unroll
    for (int o = 16; o; o >>= 1) dsum += __shfl_down_sync(0xffffffffu, dsum, o);
    if (lane == 0) atomicAdd(&sdeg, dsum);   // integer: deterministic

    unsigned bal0 = __ballot_sync(0xffffffffu, c0 != 0);
    unsigned bal1 = __ballot_sync(0xffffffffu, c1 != 0);
    if (lane == 0) { scount[w] = __popc(bal0); scount[8 + w] = __popc(bal1); }
    __syncthreads();
    if (tid == 0) {
        int acc = 0;
        #pragma unroll
        for (int s = 0; s < 16; s++) { soff[s] = acc; acc += scount[s]; }
        g_nnz[b] = acc;
        g_deg[b] = sdeg;
    }
    __syncthreads();
    unsigned ltmask = (1u << lane) - 1u;
    if (c0) {
        int p = soff[w] + __popc(bal0 & ltmask);
        g_cidx[b * RR + p] = tid;        g_ccnt[b * RR + p] = (float)c0;
    }
    if (c1) {
        int p = soff[8 + w] + __popc(bal1 & ltmask);
        g_cidx[b * RR + p] = 256 + tid;  g_ccnt[b * RR + p] = (float)c1;
    }
}

// ---------------------------------------------------------------- gather
// grid (B, NCHUNK), 64 threads (one per d). Each block sums its chunk's
// compacted entries with 4 independent accumulators (high MLP).
__global__ __launch_bounds__(64) void k_gather(const float* __restrict__ rel_emb) {
    int b = blockIdx.x;
    int c = blockIdx.y;
    int d = threadIdx.x;
    int nnz = g_nnz[b];
    const float* base = rel_emb + (size_t)b * RR * DD + d;
    const int*   cidx = g_cidx + b * RR;
    const float* ccnt = g_ccnt + b * RR;

    float a0 = 0.f, a1 = 0.f, a2 = 0.f, a3 = 0.f;
    int i = c;
    // 4-wide batches, stride NCHUNK between entries of this chunk
    while (i + 3 * NCHUNK < nnz) {
        int r0 = cidx[i];              float w0 = ccnt[i];
        int r1 = cidx[i + NCHUNK];     float w1 = ccnt[i + NCHUNK];
        int r2 = cidx[i + 2 * NCHUNK]; float w2 = ccnt[i + 2 * NCHUNK];
        int r3 = cidx[i + 3 * NCHUNK]; float w3 = ccnt[i + 3 * NCHUNK];
        float v0 = base[(size_t)r0 * DD];
        float v1 = base[(size_t)r1 * DD];
        float v2 = base[(size_t)r2 * DD];
        float v3 = base[(size_t)r3 * DD];
        a0 = fmaf(w0, v0, a0);
        a1 = fmaf(w1, v1, a1);
        a2 = fmaf(w2, v2, a2);
        a3 = fmaf(w3, v3, a3);
        i += 4 * NCHUNK;
    }
    if (i < nnz) { a0 = fmaf(ccnt[i], base[(size_t)cidx[i] * DD], a0); i += NCHUNK; }
    if (i < nnz) { a1 = fmaf(ccnt[i], base[(size_t)cidx[i] * DD], a1); i += NCHUNK; }
    if (i < nnz) { a2 = fmaf(ccnt[i], base[(size_t)cidx[i] * DD], a2); }
    g_part[(b * NCHUNK + c) * DD + d] = (a0 + a1) + (a2 + a3);   // fixed order
}

// ---------------------------------------------------------------- mlp
__global__ __launch_bounds__(128) void k_mlp(
    const float* __restrict__ rel_emb,
    const int* __restrict__ qrels,
    const float* __restrict__ W1, const float* __restrict__ b1,
    const float* __restrict__ W2, const float* __restrict__ b2,
    const float* __restrict__ W3, const float* __restrict__ b3,
    const float* __restrict__ W4, const float* __restrict__ b4,
    float* __restrict__ out, int E, float density) {
    int b = blockIdx.x;
    int tid = threadIdx.x;
    __shared__ float sx[DIN];
    __shared__ float sw[2][DD];
    __shared__ float sh1[DD];
    __shared__ float sh2[32];
    __shared__ float sg[16];

    float deg = (float)g_deg[b];
    float inv = 1.0f / fmaxf(deg, 1.0f);
    int qr = qrels[b];

    if (tid < DD) {
        // fixed-order reduction of the NCHUNK gather partials
        const float* p = g_part + (size_t)b * NCHUNK * DD + tid;
        float s = 0.f;
        #pragma unroll
        for (int c = 0; c < NCHUNK; c++) s += p[c * DD];
        sx[DD + tid] = s * inv;
        sx[tid] = rel_emb[((size_t)b * RR + qr) * DD + tid];
    }
    if (tid == 0) {
        float freq = fminf((float)g_relc[qr] / (float)E, 1.0f);
        float degn = fminf(deg / (float)E, 1.0f);
        sx[128] = freq;
        sx[129] = degn;
        sx[130] = freq;
        sx[131] = density;
    }
    __syncthreads();

    // W1: 132 -> 64, split input range across 2 half-threads, 4 accs each
    {
        int o = tid & 63;
        int h = tid >> 6;           // 0: i in [0,66), 1: i in [66,132)
        int i0 = h * 66;
        float a0 = 0.f, a1 = 0.f, a2 = 0.f, a3 = 0.f;
        const float* wcol = W1 + o;
        #pragma unroll
        for (int i = 0; i < 64; i += 4) {
            a0 = fmaf(sx[i0 + i],     wcol[(i0 + i) * 64],     a0);
            a1 = fmaf(sx[i0 + i + 1], wcol[(i0 + i + 1) * 64], a1);
            a2 = fmaf(sx[i0 + i + 2], wcol[(i0 + i + 2) * 64], a2);
            a3 = fmaf(sx[i0 + i + 3], wcol[(i0 + i + 3) * 64], a3);
        }
        a0 = fmaf(sx[i0 + 64], wcol[(i0 + 64) * 64], a0);
        a1 = fmaf(sx[i0 + 65], wcol[(i0 + 65) * 64], a1);
        sw[h][o] = (a0 + a1) + (a2 + a3);
    }
    __syncthreads();
    if (tid < DD)
        sh1[tid] = fmaxf(b1[tid] + sw[0][tid] + sw[1][tid], 0.0f);
    __syncthreads();
    if (tid < 32) {
        float a0 = b2[tid], a1 = 0.f, a2 = 0.f, a3 = 0.f;
        #pragma unroll
        for (int i = 0; i < 64; i += 4) {
            a0 = fmaf(sh1[i],     W2[i * 32 + tid],       a0);
            a1 = fmaf(sh1[i + 1], W2[(i + 1) * 32 + tid], a1);
            a2 = fmaf(sh1[i + 2], W2[(i + 2) * 32 + tid], a2);
            a3 = fmaf(sh1[i + 3], W2[(i + 3) * 32 + tid], a3);
        }
        sh2[tid] = fmaxf((a0 + a1) + (a2 + a3), 0.0f);
    }
    __syncthreads();
    if (tid < 16) {
        float a0 = b3[tid], a1 = 0.f;
        #pragma unroll
        for (int i = 0; i < 32; i += 2) {
            a0 = fmaf(sh2[i],     W3[i * 16 + tid],       a0);
            a1 = fmaf(sh2[i + 1], W3[(i + 1) * 16 + tid], a1);
        }
        sg[tid] = fmaxf(a0 + a1, 0.0f);
    }
    __syncthreads();
    if (tid == 0) {
        float acc = b4[0];
        #pragma unroll
        for (int i = 0; i < 16; i++) acc = fmaf(sg[i], W4[i], acc);
        out[b] = 1.0f / (1.0f + expf(-acc));
    }
}

// ---------------------------------------------------------------- launch
extern "C" void kernel_launch(void* const* d_in, const int* in_sizes, int n_in,
                              void* d_out, int out_size) {
    const float* rel_emb = (const float*)d_in[0];
    const int*   qrels   = (const int*)d_in[1];
    const int*   qent    = (const int*)d_in[2];
    const int*   eidx    = (const int*)d_in[3];
    const int*   etype   = (const int*)d_in[4];
    const float* W1 = (const float*)d_in[n_in - 8];
    const float* b1 = (const float*)d_in[n_in - 7];
    const float* W2 = (const float*)d_in[n_in - 6];
    const float* b2 = (const float*)d_in[n_in - 5];
    const float* W3 = (const float*)d_in[n_in - 4];
    const float* b3 = (const float*)d_in[n_in - 3];
    const float* W4 = (const float*)d_in[n_in - 2];
    const float* b4 = (const float*)d_in[n_in - 1];

    int B = in_sizes[1];          // 256
    int E = in_sizes[4];          // 3,200,000
    const int* heads = eidx;
    const int* tails = eidx + E;

    double Nd = 100000.0;         // fixed problem
    float density = (float)fmin((double)E / (Nd * Nd), 1.0);

    k_clear<<<(BB * RR + 255) / 256, 256>>>();
    k_build<<<(B + 255) / 256, 256>>>(qent, B);
    k_edges<<<592, 256>>>(heads, tails, etype, E);
    k_compact<<<B, 256>>>(qent);
    k_gather<<<dim3(B, NCHUNK), 64>>>(rel_emb);
    k_mlp<<<B, 128>>>(rel_emb, qrels,
                      W1, b1, W2, b2, W3, b3, W4, b4,
                      (float*)d_out, E, density);
}